// round 7
// baseline (speedup 1.0000x reference)
#include <cuda_runtime.h>

#define NMAX 100000
#define EMAX 1600000
#define DD   128

// ---------------- device scratch (symbol-only access, no allocations) -----
__device__ __align__(16) float g_t[(size_t)NMAX * DD];   // h @ W_l^T
__device__ __align__(16) float g_z[(size_t)NMAX * DD];   // h @ W_r^T + b
__device__ __align__(16) float g_h[(size_t)NMAX * DD];   // layer activations
__device__ int   g_rowptr[NMAX + 1];
__device__ int   g_cursor[NMAX];
__device__ int   g_col[EMAX];
__device__ float g_inv[NMAX];
__device__ int   g_cnt[NMAX];
__device__ int   g_wide;   // 1 if edge_index is int64-layout, 0 if int32

// ---------------- copies (param -> symbol) --------------------------------
__global__ void copy_in_kernel(const float4* __restrict__ x, int n4) {
    int i = blockIdx.x * blockDim.x + threadIdx.x;
    if (i < n4) ((float4*)g_h)[i] = x[i];
}

// ---------------- edge dtype detection ------------------------------------
// Safe under both layouts: probes only words [0, 2E). If the buffer is
// int64 [2,E], words at odd indices are the high halves of src values
// (< 2^31) => all zero. If int32, odd words are random node ids => OR != 0.
__global__ void detect_kernel(const int* __restrict__ ei, int E) {
    __shared__ int s_or;
    if (threadIdx.x == 0) s_or = 0;
    __syncthreads();
    int acc = 0;
    for (int i = blockIdx.x * blockDim.x + threadIdx.x; i < E; i += gridDim.x * blockDim.x)
        acc |= ei[2 * i + 1];
    if (acc) atomicOr(&s_or, 1);
    __syncthreads();
    if (threadIdx.x == 0 && s_or) g_wide = 0;   // pre-set to 1 by init kernel
}

__global__ void init_flag_kernel() { g_wide = 1; }

// ---------------- CSR build ----------------
__global__ void zero_cnt_kernel(int n) {
    int i = blockIdx.x * blockDim.x + threadIdx.x;
    if (i < n) g_cnt[i] = 0;
}

__global__ void hist_kernel(const int* __restrict__ ei, int E) {
    int e = blockIdx.x * blockDim.x + threadIdx.x;
    if (e < E) {
        int dst = g_wide ? ei[2 * ((size_t)E + e)] : ei[(size_t)E + e];
        atomicAdd(&g_cnt[dst], 1);
    }
}

// single-block scan over n counters -> rowptr (exclusive), cursor copy, inv
__global__ void scan_kernel(int n) {
    __shared__ int sh[1024];
    __shared__ int s_carry;
    if (threadIdx.x == 0) s_carry = 0;
    __syncthreads();
    for (int base = 0; base < n; base += 1024) {
        int i = base + threadIdx.x;
        int v = (i < n) ? g_cnt[i] : 0;
        sh[threadIdx.x] = v;
        __syncthreads();
        for (int off = 1; off < 1024; off <<= 1) {
            int t = 0;
            if ((int)threadIdx.x >= off) t = sh[threadIdx.x - off];
            __syncthreads();
            sh[threadIdx.x] += t;
            __syncthreads();
        }
        int incl = sh[threadIdx.x] + s_carry;
        if (i < n) {
            g_rowptr[i + 1] = incl;
            g_cursor[i]     = incl - v;
            g_inv[i]        = 1.0f / fmaxf((float)v, 1.0f);
        }
        __syncthreads();
        if (threadIdx.x == 1023) s_carry = incl;
        __syncthreads();
    }
    if (threadIdx.x == 0) g_rowptr[0] = 0;
}

__global__ void fill_kernel(const int* __restrict__ ei, int E) {
    int e = blockIdx.x * blockDim.x + threadIdx.x;
    if (e < E) {
        int wide = g_wide;
        int src = wide ? ei[2 * (size_t)e]        : ei[e];
        int dst = wide ? ei[2 * ((size_t)E + e)]  : ei[(size_t)E + e];
        int pos = atomicAdd(&g_cursor[dst], 1);
        g_col[pos] = src;
    }
}

// ---------------- dual GEMM: g_t = g_h@Wl^T ; g_z = g_h@Wr^T + b ----------
// Tile: 64 rows x 64 cols (blockIdx.y = n-half). K chunked by 32.
// Static shared only: As 8KB + Wls 9.2KB + Wrs 9.2KB = 26.4KB.
__global__ __launch_bounds__(256)
void gemm_dual_kernel(const float* __restrict__ Wl,
                      const float* __restrict__ Wr,
                      const float* __restrict__ bias,
                      int n)
{
    __shared__ float As[64 * 32];      // [row][k-chunk], pitch 32
    __shared__ float Wls[64 * 36];     // [n-local][k-chunk], pitch 36 (9 float4)
    __shared__ float Wrs[64 * 36];

    const int tid = threadIdx.x;
    const int tx = tid & 31;           // n-lane
    const int ty = tid >> 5;           // row group 0..7 (8 rows each)
    const int row0 = blockIdx.x * 64;
    const int ncol0 = blockIdx.y * 64; // n-half base

    float accl[8][2], accr[8][2];
    #pragma unroll
    for (int i = 0; i < 8; i++) {
        accl[i][0] = accl[i][1] = 0.f;
        accr[i][0] = accr[i][1] = 0.f;
    }

    for (int kc = 0; kc < 4; kc++) {
        // load A k-chunk: 64 rows x 8 float4 = 512 float4
        #pragma unroll
        for (int l = 0; l < 2; l++) {
            int i = tid + l * 256;
            int r = i >> 3, c4 = i & 7;
            float4 v = make_float4(0.f, 0.f, 0.f, 0.f);
            if (row0 + r < n)
                v = ((const float4*)g_h)[(size_t)(row0 + r) * 32 + kc * 8 + c4];
            ((float4*)As)[r * 8 + c4] = v;
        }
        // load W halves: 64 n-rows x 8 float4 each
        #pragma unroll
        for (int l = 0; l < 2; l++) {
            int i = tid + l * 256;
            int nr = i >> 3, c4 = i & 7;
            ((float4*)(Wls + nr * 36))[c4] =
                ((const float4*)Wl)[(ncol0 + nr) * 32 + kc * 8 + c4];
            ((float4*)(Wrs + nr * 36))[c4] =
                ((const float4*)Wr)[(ncol0 + nr) * 32 + kc * 8 + c4];
        }
        __syncthreads();

        #pragma unroll
        for (int k4 = 0; k4 < 8; k4++) {
            float4 a[8];
            #pragma unroll
            for (int i = 0; i < 8; i++)
                a[i] = ((const float4*)As)[(ty * 8 + i) * 8 + k4];  // broadcast
            #pragma unroll
            for (int j = 0; j < 2; j++) {
                int nn = tx + 32 * j;
                float4 wl = ((const float4*)(Wls + nn * 36))[k4];
                float4 wr = ((const float4*)(Wrs + nn * 36))[k4];
                #pragma unroll
                for (int i = 0; i < 8; i++) {
                    float vl = accl[i][j], vr = accr[i][j];
                    vl = fmaf(a[i].x, wl.x, vl); vr = fmaf(a[i].x, wr.x, vr);
                    vl = fmaf(a[i].y, wl.y, vl); vr = fmaf(a[i].y, wr.y, vr);
                    vl = fmaf(a[i].z, wl.z, vl); vr = fmaf(a[i].z, wr.z, vr);
                    vl = fmaf(a[i].w, wl.w, vl); vr = fmaf(a[i].w, wr.w, vr);
                    accl[i][j] = vl; accr[i][j] = vr;
                }
            }
        }
        __syncthreads();
    }

    // epilogue
    #pragma unroll
    for (int j = 0; j < 2; j++) {
        int c = ncol0 + tx + 32 * j;
        float bv = bias[c];
        #pragma unroll
        for (int i = 0; i < 8; i++) {
            int r = row0 + ty * 8 + i;
            if (r < n) {
                g_t[(size_t)r * DD + c] = accl[i][j];
                g_z[(size_t)r * DD + c] = accr[i][j] + bv;
            }
        }
    }
}

// ---------------- aggregate + finalize: dst = [relu](mean_agg(t) + z) -----
// TO_OUT: write to the out parameter (harness d_out); otherwise write g_h.
template <bool RELU, bool TO_OUT>
__global__ void aggregate_kernel(float* __restrict__ out, int n)
{
    int node = (blockIdx.x * blockDim.x + threadIdx.x) >> 5;
    int lane = threadIdx.x & 31;
    if (node >= n) return;

    int beg = g_rowptr[node];
    int end = g_rowptr[node + 1];
    const float4* t4 = (const float4*)g_t;

    float4 acc = make_float4(0.f, 0.f, 0.f, 0.f);
    int j = beg;
    for (; j + 4 <= end; j += 4) {
        int s0 = g_col[j], s1 = g_col[j + 1], s2 = g_col[j + 2], s3 = g_col[j + 3];
        float4 v0 = t4[(size_t)s0 * 32 + lane];
        float4 v1 = t4[(size_t)s1 * 32 + lane];
        float4 v2 = t4[(size_t)s2 * 32 + lane];
        float4 v3 = t4[(size_t)s3 * 32 + lane];
        acc.x += (v0.x + v1.x) + (v2.x + v3.x);
        acc.y += (v0.y + v1.y) + (v2.y + v3.y);
        acc.z += (v0.z + v1.z) + (v2.z + v3.z);
        acc.w += (v0.w + v1.w) + (v2.w + v3.w);
    }
    for (; j < end; j++) {
        int s = g_col[j];
        float4 v = t4[(size_t)s * 32 + lane];
        acc.x += v.x; acc.y += v.y; acc.z += v.z; acc.w += v.w;
    }

    float inv = g_inv[node];
    float4 z = ((const float4*)g_z)[(size_t)node * 32 + lane];
    float4 o;
    o.x = fmaf(acc.x, inv, z.x);
    o.y = fmaf(acc.y, inv, z.y);
    o.z = fmaf(acc.z, inv, z.z);
    o.w = fmaf(acc.w, inv, z.w);
    if (RELU) {
        o.x = fmaxf(o.x, 0.f); o.y = fmaxf(o.y, 0.f);
        o.z = fmaxf(o.z, 0.f); o.w = fmaxf(o.w, 0.f);
    }
    if (TO_OUT) ((float4*)out)[(size_t)node * 32 + lane] = o;
    else        ((float4*)g_h)[(size_t)node * 32 + lane] = o;
}

// ---------------- launch ----------------
extern "C" void kernel_launch(void* const* d_in, const int* in_sizes, int n_in,
                              void* d_out, int out_size)
{
    const float* x   = (const float*)d_in[0];
    const int*   ei  = (const int*)d_in[1];     // int32 expected (JAX x64 off)
    const float* Wl1 = (const float*)d_in[2];
    const float* Wr1 = (const float*)d_in[3];
    const float* b1  = (const float*)d_in[4];
    const float* Wl2 = (const float*)d_in[5];
    const float* Wr2 = (const float*)d_in[6];
    const float* b2  = (const float*)d_in[7];
    const float* Wl3 = (const float*)d_in[8];
    const float* Wr3 = (const float*)d_in[9];
    const float* b3  = (const float*)d_in[10];
    float* out = (float*)d_out;

    const int N = in_sizes[0] / DD;
    const int E = in_sizes[1] / 2;

    // ---- stage input into symbol scratch ----
    const int n4 = N * 32;
    copy_in_kernel<<<(n4 + 255) / 256, 256>>>((const float4*)x, n4);

    // ---- edge dtype detection (probes only the first 2E words: safe) ----
    init_flag_kernel<<<1, 1>>>();
    detect_kernel<<<256, 256>>>(ei, E);

    // ---- CSR build ----
    zero_cnt_kernel<<<(N + 255) / 256, 256>>>(N);
    hist_kernel<<<(E + 255) / 256, 256>>>(ei, E);
    scan_kernel<<<1, 1024>>>(N);
    fill_kernel<<<(E + 255) / 256, 256>>>(ei, E);

    dim3 gemm_grid((N + 63) / 64, 2);
    const int agg_grid = (N + 7) / 8;   // 8 warps/block, 1 warp/node

    // ---- layer 1 ----
    gemm_dual_kernel<<<gemm_grid, 256>>>(Wl1, Wr1, b1, N);
    aggregate_kernel<true , false><<<agg_grid, 256>>>(out, N);
    // ---- layer 2 ----
    gemm_dual_kernel<<<gemm_grid, 256>>>(Wl2, Wr2, b2, N);
    aggregate_kernel<true , false><<<agg_grid, 256>>>(out, N);
    // ---- layer 3 ----
    gemm_dual_kernel<<<gemm_grid, 256>>>(Wl3, Wr3, b3, N);
    aggregate_kernel<false, true ><<<agg_grid, 256>>>(out, N);
}